// round 11
// baseline (speedup 1.0000x reference)
#include <cuda_runtime.h>
#include <cuda_bf16.h>

#define N_PTS 16384
#define KNN   16

__device__ int    g_nbr[N_PTS * KNN];
__device__ float  g_h0[N_PTS * 6];
__device__ float4 g_pos4[N_PTS];

// ---------------- packed f32x2 helpers ----------------
__device__ __forceinline__ unsigned long long pk2(float lo, float hi) {
    unsigned long long r;
    asm("mov.b64 %0, {%1, %2};" : "=l"(r) : "f"(lo), "f"(hi));
    return r;
}
__device__ __forceinline__ void upk2(unsigned long long v, float& lo, float& hi) {
    asm("mov.b64 {%0, %1}, %2;" : "=f"(lo), "=f"(hi) : "l"(v));
}
__device__ __forceinline__ void fma2(unsigned long long& d, unsigned long long a,
                                     unsigned long long b) {
    asm("fma.rn.f32x2 %0, %1, %2, %0;" : "+l"(d) : "l"(a), "l"(b));
}
__device__ __forceinline__ unsigned long long add2(unsigned long long a,
                                                   unsigned long long b) {
    unsigned long long d;
    asm("add.rn.f32x2 %0, %1, %2;" : "=l"(d) : "l"(a), "l"(b));
    return d;
}
__device__ __forceinline__ unsigned long long mul2(unsigned long long a,
                                                   unsigned long long b) {
    unsigned long long d;
    asm("mul.rn.f32x2 %0, %1, %2;" : "=l"(d) : "l"(a), "l"(b));
    return d;
}

// ---------------------------------------------------------------------------
// prep: pos -> float4 (x, y, z, |p|^2)  — exact fp32, same algebra as reference
// ---------------------------------------------------------------------------
__global__ void prep_kernel(const float* __restrict__ pos, float4* __restrict__ p4)
{
    const int i = blockIdx.x * 256 + threadIdx.x;
    if (i < N_PTS) {
        const float x = pos[3 * i], y = pos[3 * i + 1], z = pos[3 * i + 2];
        p4[i] = make_float4(x, y, z, fmaf(x, x, fmaf(y, y, z * z)));
    }
}

// ---------------------------------------------------------------------------
// kNN: 4 lanes/query, candidates pre-packed in pairs in SMEM (packed f32x2
// distance math, exact fp32). Branch-free register insertion network; shared
// prune threshold across the 4 sibling lanes; exact 4-way merge on
// (sortable-d2 | idx) u64 keys.
// ---------------------------------------------------------------------------
__device__ __forceinline__ void knn_insert(float d2, int idx,
                                           float (&bestd)[KNN], int (&besti)[KNN])
{
#pragma unroll
    for (int r = KNN - 1; r >= 1; r--) {
        const bool keep  = bestd[r] <= d2;
        const bool shift = bestd[r - 1] > d2;
        bestd[r] = keep ? bestd[r] : (shift ? bestd[r - 1] : d2);
        besti[r] = keep ? besti[r] : (shift ? besti[r - 1] : idx);
    }
    const bool keep = bestd[0] <= d2;
    bestd[0] = keep ? bestd[0] : d2;
    besti[0] = keep ? besti[0] : idx;
}

__global__ void __launch_bounds__(256) knn_kernel(const float4* __restrict__ p4,
                                                  int* __restrict__ nbr)
{
    // 32KB shared, phase-reused: packed tiles (16KB) then merge lists (32KB)
    __shared__ __align__(16) unsigned char sraw[32768];
    ulonglong2 (*sXY)[128] = reinterpret_cast<ulonglong2(*)[128]>(sraw);
    ulonglong2 (*sZW)[128] = reinterpret_cast<ulonglong2(*)[128]>(sraw + 8192);
    unsigned long long* lists = reinterpret_cast<unsigned long long*>(sraw);

    const int tid = threadIdx.x;
    const int s   = tid & 3;          // split 0..3
    const int ql  = tid >> 2;         // query-local 0..63
    const int q   = blockIdx.x * 64 + ql;
    const float4 me = p4[q];

    const unsigned long long qx = pk2(me.x, me.x);
    const unsigned long long qy = pk2(me.y, me.y);
    const unsigned long long qz = pk2(me.z, me.z);
    const unsigned long long qs = pk2(me.w, me.w);
    const unsigned long long m2 = pk2(-2.0f, -2.0f);

    float bestd[KNN];
    int   besti[KNN];
#pragma unroll
    for (int r = 0; r < KNN; r++) { bestd[r] = 3.4e38f; besti[r] = 0; }
    float thr_g = 3.4e38f;

    const int cbase = s * 4096;
    for (int it = 0; it < 16; it++) {
        __syncthreads();
#pragma unroll
        for (int u = 0; u < 2; u++) {
            const int gp = u * 256 + tid;          // pair id 0..511
            const int ls = gp >> 7, lp = gp & 127;
            const float4 c0 = p4[ls * 4096 + it * 256 + 2 * lp];
            const float4 c1 = p4[ls * 4096 + it * 256 + 2 * lp + 1];
            sXY[ls][lp] = make_ulonglong2(pk2(c0.x, c1.x), pk2(c0.y, c1.y));
            sZW[ls][lp] = make_ulonglong2(pk2(c0.z, c1.z), pk2(c0.w, c1.w));
        }
        __syncthreads();

        const int ibase = cbase + it * 256;
#pragma unroll 4
        for (int p = 0; p < 128; p++) {
            const ulonglong2 xy = sXY[s][p];
            const ulonglong2 zw = sZW[s][p];
            unsigned long long dot = mul2(qx, xy.x);
            fma2(dot, qy, xy.y);
            fma2(dot, qz, zw.x);
            unsigned long long d2p = add2(qs, zw.y);   // sq_i + sq_j
            fma2(d2p, m2, dot);                        // + (-2)*dot  (fma)
            float d20, d21;
            upk2(d2p, d20, d21);
            if (fminf(d20, d21) <= thr_g) {
                const int idx = ibase + 2 * p;
                if (d20 <= thr_g) knn_insert(d20, idx, bestd, besti);
                if (d21 <= thr_g) knn_insert(d21, idx + 1, bestd, besti);
                thr_g = fminf(thr_g, bestd[KNN - 1]);
            }
        }
        float t = bestd[KNN - 1];
        t = fminf(t, __shfl_xor_sync(0xffffffffu, t, 1));
        t = fminf(t, __shfl_xor_sync(0xffffffffu, t, 2));
        thr_g = t;
    }

    // ---- exact 4-way merge ----
    __syncthreads();
    unsigned long long* mylist = lists + (ql * 4 + s) * 16;
#pragma unroll
    for (int r = 0; r < KNN; r++) {
        unsigned int db = __float_as_uint(bestd[r]);
        db ^= (db & 0x80000000u) ? 0xFFFFFFFFu : 0x80000000u;  // sortable bits
        mylist[r] = ((unsigned long long)db << 32) | (unsigned int)besti[r];
    }
    __syncwarp();

    int p = 0;
#pragma unroll 1
    for (int r = 0; r < KNN; r++) {
        unsigned long long k = (p < KNN) ? mylist[p] : ~0ull;
        unsigned long long o = __shfl_xor_sync(0xffffffffu, k, 1);
        unsigned long long km = (k < o) ? k : o;
        o = __shfl_xor_sync(0xffffffffu, km, 2);
        km = (km < o) ? km : o;
        if (k == km) {
            nbr[q * KNN + r] = (int)(unsigned int)(km & 0xffffffffu);
            p++;
        }
    }
}

// ---------------------------------------------------------------------------
__global__ void concat_kernel(const float* __restrict__ pos,
                              const float* __restrict__ normal,
                              float* __restrict__ h0)
{
    const int i = blockIdx.x * 256 + threadIdx.x;
    if (i < N_PTS) {
#pragma unroll
        for (int c = 0; c < 3; c++) {
            h0[i * 6 + c]     = pos[i * 3 + c];
            h0[i * 6 + 3 + c] = normal[i * 3 + c];
        }
    }
}

// ---------------------------------------------------------------------------
// SMEM-tiled fused PointNetConv (exact fp32, as in the passing R5/R6 build).
// ---------------------------------------------------------------------------
template <int CIN_X, int C1, int C2>
__global__ void __launch_bounds__(256) conv_kernel(
    const float* __restrict__ x, const float* __restrict__ pos,
    const int* __restrict__ nbr,
    const float* __restrict__ Wa, const float* __restrict__ ba,
    const float* __restrict__ gmm, const float* __restrict__ bet,
    const float* __restrict__ Wb, const float* __restrict__ bb,
    float* __restrict__ out)
{
    constexpr int CIN = CIN_X + 3;
    constexpr int EP  = 260;
    constexpr int NC  = C1 / 8;
    constexpr int NG  = NC / 8;
    constexpr int R0F = (CIN * EP + CIN * C1 > C1 * EP) ? (CIN * EP + CIN * C1)
                                                        : (C1 * EP);

    extern __shared__ float smf[];
    float* sM  = smf;
    float* sWa = smf + CIN * EP;
    float* sH  = smf;
    float* sWb = smf + R0F;
    float* sba = sWb + C1 * C2;
    float* sg  = sba + C1;
    float* sbe = sg + C1;
    float* sbb = sbe + C1;

    const int tid = threadIdx.x;
    const int eo  = tid >> 3;
    const int co  = tid & 7;

    for (int i = tid; i < CIN * C1; i += 256) sWa[i] = Wa[i];
    for (int i = tid; i < C1 * C2; i += 256) sWb[i] = Wb[i];
    if (tid < C1) { sba[tid] = ba[tid]; sg[tid] = gmm[tid]; sbe[tid] = bet[tid]; }
    if (tid < C2) sbb[tid] = bb[tid];

    {
        const int e    = tid;
        const int node = (blockIdx.x << 4) + (e >> 4);
        const int j    = nbr[(node << 4) + (e & 15)];
        if constexpr (CIN_X == 6) {
            const float2* xj2 = (const float2*)(x + (long)j * 6);
#pragma unroll
            for (int p = 0; p < 3; p++) {
                const float2 v = __ldg(xj2 + p);
                sM[(2 * p) * EP + e]     = v.x;
                sM[(2 * p + 1) * EP + e] = v.y;
            }
        } else {
            const float4* xj4 = (const float4*)(x + (long)j * CIN_X);
#pragma unroll
            for (int p = 0; p < CIN_X / 4; p++) {
                const float4 v = __ldg(xj4 + p);
                sM[(4 * p) * EP + e]     = v.x;
                sM[(4 * p + 1) * EP + e] = v.y;
                sM[(4 * p + 2) * EP + e] = v.z;
                sM[(4 * p + 3) * EP + e] = v.w;
            }
        }
        sM[(CIN_X + 0) * EP + e] = pos[3 * j]     - pos[3 * node];
        sM[(CIN_X + 1) * EP + e] = pos[3 * j + 1] - pos[3 * node + 1];
        sM[(CIN_X + 2) * EP + e] = pos[3 * j + 2] - pos[3 * node + 2];
    }
    __syncthreads();

    unsigned long long acc[NC][4];
#pragma unroll
    for (int c = 0; c < NC; c++) {
        const float b = sba[co * NC + c];
        const unsigned long long bd = pk2(b, b);
#pragma unroll
        for (int ep = 0; ep < 4; ep++) acc[c][ep] = bd;
    }
#pragma unroll 2
    for (int k = 0; k < CIN; k++) {
        const ulonglong2 mv0 = *(const ulonglong2*)(sM + k * EP + 8 * eo);
        const ulonglong2 mv1 = *(const ulonglong2*)(sM + k * EP + 8 * eo + 4);
        float wv[NC];
#pragma unroll
        for (int q4 = 0; q4 < NC / 4; q4++) {
            const float4 t = *(const float4*)(sWa + k * C1 + co * NC + 4 * q4);
            wv[4 * q4] = t.x; wv[4 * q4 + 1] = t.y;
            wv[4 * q4 + 2] = t.z; wv[4 * q4 + 3] = t.w;
        }
#pragma unroll
        for (int c = 0; c < NC; c++) {
            const unsigned long long wd = pk2(wv[c], wv[c]);
            fma2(acc[c][0], mv0.x, wd);
            fma2(acc[c][1], mv0.y, wd);
            fma2(acc[c][2], mv1.x, wd);
            fma2(acc[c][3], mv1.y, wd);
        }
    }
    __syncthreads();

#pragma unroll
    for (int gi = 0; gi < NG; gi++) {
        const int cb = gi * 8;
#pragma unroll
        for (int ep = 0; ep < 4; ep++) {
            unsigned long long ssum = acc[cb][ep];
            unsigned long long qq = mul2(acc[cb][ep], acc[cb][ep]);
#pragma unroll
            for (int c = 1; c < 8; c++) {
                ssum = add2(ssum, acc[cb + c][ep]);
                fma2(qq, acc[cb + c][ep], acc[cb + c][ep]);
            }
            float s0, s1, q0, q1;
            upk2(ssum, s0, s1);
            upk2(qq, q0, q1);
            const float mu0 = s0 * 0.125f, mu1 = s1 * 0.125f;
            const float rs0 = rsqrtf(fmaf(-mu0, mu0, q0 * 0.125f) + 1e-5f);
            const float rs1 = rsqrtf(fmaf(-mu1, mu1, q1 * 0.125f) + 1e-5f);
#pragma unroll
            for (int c = 0; c < 8; c++) {
                const int gc = co * NC + cb + c;
                const float gam = sg[gc], bet_ = sbe[gc];
                float v0, v1;
                upk2(acc[cb + c][ep], v0, v1);
                v0 = fmaxf(fmaf((v0 - mu0) * rs0, gam, bet_), 0.f);
                v1 = fmaxf(fmaf((v1 - mu1) * rs1, gam, bet_), 0.f);
                *(float2*)(sH + gc * EP + 8 * eo + 2 * ep) = make_float2(v0, v1);
            }
        }
    }
    __syncthreads();

    unsigned long long a2[NC][4];
#pragma unroll
    for (int c = 0; c < NC; c++) {
        const float b = sbb[co * NC + c];
        const unsigned long long bd = pk2(b, b);
#pragma unroll
        for (int ep = 0; ep < 4; ep++) a2[c][ep] = bd;
    }
#pragma unroll 2
    for (int k = 0; k < C1; k++) {
        const ulonglong2 hv0 = *(const ulonglong2*)(sH + k * EP + 8 * eo);
        const ulonglong2 hv1 = *(const ulonglong2*)(sH + k * EP + 8 * eo + 4);
        float wv[NC];
#pragma unroll
        for (int q4 = 0; q4 < NC / 4; q4++) {
            const float4 t = *(const float4*)(sWb + k * C2 + co * NC + 4 * q4);
            wv[4 * q4] = t.x; wv[4 * q4 + 1] = t.y;
            wv[4 * q4 + 2] = t.z; wv[4 * q4 + 3] = t.w;
        }
#pragma unroll
        for (int c = 0; c < NC; c++) {
            const unsigned long long wd = pk2(wv[c], wv[c]);
            fma2(a2[c][0], hv0.x, wd);
            fma2(a2[c][1], hv0.y, wd);
            fma2(a2[c][2], hv1.x, wd);
            fma2(a2[c][3], hv1.y, wd);
        }
    }

    float vmax[NC];
#pragma unroll
    for (int c = 0; c < NC; c++) {
        float m0, m1, t0, t1;
        upk2(a2[c][0], m0, m1);
        m0 = fmaxf(m0, m1);
        upk2(a2[c][1], t0, t1);
        m0 = fmaxf(m0, fmaxf(t0, t1));
        upk2(a2[c][2], t0, t1);
        m0 = fmaxf(m0, fmaxf(t0, t1));
        upk2(a2[c][3], t0, t1);
        m0 = fmaxf(m0, fmaxf(t0, t1));
        vmax[c] = m0;
    }
#pragma unroll
    for (int c = 0; c < NC; c++)
        vmax[c] = fmaxf(vmax[c], __shfl_xor_sync(0xffffffffu, vmax[c], 8));

    if (!(eo & 1)) {
        const int node = (blockIdx.x << 4) + (eo >> 1);
        float* op = out + (long)node * C2 + co * NC;
#pragma unroll
        for (int q4 = 0; q4 < NC / 4; q4++) {
            *(float4*)(op + 4 * q4) = make_float4(
                fmaxf(vmax[4 * q4], 0.f),     fmaxf(vmax[4 * q4 + 1], 0.f),
                fmaxf(vmax[4 * q4 + 2], 0.f), fmaxf(vmax[4 * q4 + 3], 0.f));
        }
    }
}

// ---------------------------------------------------------------------------
template <int CIN_X, int C1, int C2>
static int conv_smem_bytes()
{
    constexpr int CIN = CIN_X + 3;
    constexpr int EP  = 260;
    constexpr int R0F = (CIN * EP + CIN * C1 > C1 * EP) ? (CIN * EP + CIN * C1)
                                                        : (C1 * EP);
    return (R0F + C1 * C2 + 3 * C1 + C2) * 4;
}

extern "C" void kernel_launch(void* const* d_in, const int* in_sizes, int n_in,
                              void* d_out, int out_size)
{
    const float* pos    = (const float*)d_in[0];
    const float* normal = (const float*)d_in[1];
    const float* W1a = (const float*)d_in[2];
    const float* b1a = (const float*)d_in[3];
    const float* g1  = (const float*)d_in[4];
    const float* be1 = (const float*)d_in[5];
    const float* W1b = (const float*)d_in[6];
    const float* b1b = (const float*)d_in[7];
    const float* W2a = (const float*)d_in[8];
    const float* b2a = (const float*)d_in[9];
    const float* g2  = (const float*)d_in[10];
    const float* be2 = (const float*)d_in[11];
    const float* W2b = (const float*)d_in[12];
    const float* b2b = (const float*)d_in[13];
    const float* W3a = (const float*)d_in[14];
    const float* b3a = (const float*)d_in[15];
    const float* g3  = (const float*)d_in[16];
    const float* be3 = (const float*)d_in[17];
    const float* W3b = (const float*)d_in[18];
    const float* b3b = (const float*)d_in[19];

    float* out = (float*)d_out;
    float* h1 = out;
    float* h2 = out + (size_t)N_PTS * 64;
    float* h3 = out + (size_t)N_PTS * 128;

    void *nbr_p = nullptr, *h0_p = nullptr, *p4_p = nullptr;
    cudaGetSymbolAddress(&nbr_p, g_nbr);
    cudaGetSymbolAddress(&h0_p, g_h0);
    cudaGetSymbolAddress(&p4_p, g_pos4);
    int*    nbr = (int*)nbr_p;
    float*  h0  = (float*)h0_p;
    float4* p4  = (float4*)p4_p;

    const int sm1 = conv_smem_bytes<6, 64, 64>();
    const int sm2 = conv_smem_bytes<64, 64, 64>();
    const int sm3 = conv_smem_bytes<64, 128, 128>();

    cudaFuncSetAttribute(conv_kernel<6, 64, 64>,
                         cudaFuncAttributeMaxDynamicSharedMemorySize, sm1);
    cudaFuncSetAttribute(conv_kernel<64, 64, 64>,
                         cudaFuncAttributeMaxDynamicSharedMemorySize, sm2);
    cudaFuncSetAttribute(conv_kernel<64, 128, 128>,
                         cudaFuncAttributeMaxDynamicSharedMemorySize, sm3);

    prep_kernel<<<N_PTS / 256, 256>>>(pos, p4);
    knn_kernel<<<N_PTS / 64, 256>>>(p4, nbr);
    concat_kernel<<<N_PTS / 256, 256>>>(pos, normal, h0);

    conv_kernel<6, 64, 64><<<N_PTS / 16, 256, sm1>>>(
        h0, pos, nbr, W1a, b1a, g1, be1, W1b, b1b, h1);
    conv_kernel<64, 64, 64><<<N_PTS / 16, 256, sm2>>>(
        h1, pos, nbr, W2a, b2a, g2, be2, W2b, b2b, h2);
    conv_kernel<64, 128, 128><<<N_PTS / 16, 256, sm3>>>(
        h2, pos, nbr, W3a, b3a, g3, be3, W3b, b3b, h3);
}